// round 4
// baseline (speedup 1.0000x reference)
#include <cuda_runtime.h>

// -------- problem constants (shapes fixed by the dataset) --------
#define MAXN 50000   // N_NODES
// D_NODE = 128, HID = 256, D_OUT = 256

// -------- scratch: __device__ globals (no allocations allowed) --------
__device__ float g_sums[MAXN * 256];  // scatter-sum of edge MLP outputs, [N,256]
__device__ int   g_cnt [MAXN];        // in-degree per node
__device__ int   g_idx64;             // 1 if edge_index buffer is int64, 0 if int32

// ======================================================================
// Kernel -1: detect index dtype.
// If int64 (little-endian), every odd 32-bit word is the high half of a
// value < 50000 -> 0. If int32, odd words are random node indices.
// ======================================================================
__global__ void detect_idx_kernel(const int* __restrict__ ei_raw) {
    __shared__ int any_nonzero;
    if (threadIdx.x == 0) any_nonzero = 0;
    __syncthreads();
    // first 1024 odd words are always within bounds for either dtype
    for (int i = threadIdx.x; i < 1024; i += blockDim.x)
        if (ei_raw[2 * i + 1] != 0) any_nonzero = 1;
    __syncthreads();
    if (threadIdx.x == 0) g_idx64 = (any_nonzero == 0) ? 1 : 0;
}

__device__ __forceinline__ int load_idx(const void* ei, long long pos, int nmax) {
    int v = g_idx64 ? (int)((const long long*)ei)[pos]
                    : ((const int*)ei)[pos];
    // defensive clamp: never fault on a bad index
    return min(max(v, 0), nmax - 1);
}

// ======================================================================
// Kernel 0: zero the scratch
// ======================================================================
__global__ void zero_kernel(int n_nodes) {
    int tid    = blockIdx.x * blockDim.x + threadIdx.x;
    int stride = gridDim.x * blockDim.x;
    int tot4 = n_nodes * 64;  // (n*256)/4
    float4* s4 = (float4*)g_sums;
    float4 z = make_float4(0.f, 0.f, 0.f, 0.f);
    for (int i = tid; i < tot4; i += stride) s4[i] = z;
    for (int i = tid; i < n_nodes; i += stride) g_cnt[i] = 0;
}

// ======================================================================
// Kernel 1: edge MLP (fused 2-layer) + atomic scatter-add + degree count
//   tile = 64 edges, 256 threads, each thread owns an 8x8 micro-tile.
//   smem: buf[64*256] input tile (later overwritten with H1),
//         wbuf[16*256] staged weight chunk.
// ======================================================================
__global__ __launch_bounds__(256, 2)
void edge_mlp_kernel(const float* __restrict__ x,
                     const void* __restrict__ edge_index,
                     const float* __restrict__ edge_attr,
                     const float* __restrict__ w1a, const float* __restrict__ b1a,
                     const float* __restrict__ w1b, const float* __restrict__ b1b,
                     int E, int N)
{
    extern __shared__ float smem[];
    float* buf  = smem;             // 64 * 256
    float* wbuf = smem + 64 * 256;  // 16 * 256
    __shared__ int srow[64];
    __shared__ int scol[64];

    const int tid = threadIdx.x;
    const int er  = tid >> 5;   // 0..7  (edge-row group: edges er*8 .. er*8+7)
    const int cg  = tid & 31;   // 0..31 (col group: cols cg*8 .. cg*8+7)
    const int e0  = blockIdx.x * 64;
    const int ecnt = min(64, E - e0);

    // stage row/col indices; count degrees
    if (tid < 64) {
        int r = -1, c = -1;
        if (tid < ecnt) {
            r = load_idx(edge_index, (long long)(e0 + tid), N);
            c = load_idx(edge_index, (long long)E + e0 + tid, N);
            atomicAdd(&g_cnt[c], 1);
        }
        srow[tid] = r;
        scol[tid] = c;
    }
    __syncthreads();

    // gather input tile: [e][0:128) = x[row[e]], [e][128:256) = edge_attr[e]
    for (int idx = tid; idx < 64 * 32; idx += 256) {
        int e = idx >> 5, c4 = idx & 31;
        float4 v = make_float4(0.f, 0.f, 0.f, 0.f);
        if (e < ecnt) {
            long long r = srow[e];
            v = *(const float4*)(x + r * 128 + c4 * 4);
        }
        *(float4*)(buf + e * 256 + c4 * 4) = v;
    }
    for (int idx = tid; idx < 64 * 32; idx += 256) {
        int e = idx >> 5, c4 = idx & 31;
        float4 v = make_float4(0.f, 0.f, 0.f, 0.f);
        if (e < ecnt)
            v = *(const float4*)(edge_attr + (long long)(e0 + e) * 128 + c4 * 4);
        *(float4*)(buf + e * 256 + 128 + c4 * 4) = v;
    }

    float acc[8][8];
    #pragma unroll
    for (int i = 0; i < 8; i++)
        #pragma unroll
        for (int j = 0; j < 8; j++) acc[i][j] = 0.f;

    // ---- GEMM1: H1 = buf(64x256) @ w1a(256x256) ----
    for (int k0 = 0; k0 < 256; k0 += 16) {
        __syncthreads();  // previous chunk consumed (also covers initial tile load)
        const float4* wsrc = (const float4*)(w1a + k0 * 256);
        float4* wd = (float4*)wbuf;
        #pragma unroll
        for (int t = 0; t < 4; t++) wd[tid + t * 256] = wsrc[tid + t * 256];
        __syncthreads();
        #pragma unroll
        for (int kk = 0; kk < 16; kk++) {
            float a[8];
            #pragma unroll
            for (int i = 0; i < 8; i++)
                a[i] = buf[(er * 8 + i) * 256 + k0 + kk];   // warp-broadcast
            float4 b0 = *(float4*)(wbuf + kk * 256 + cg * 8);
            float4 b1 = *(float4*)(wbuf + kk * 256 + cg * 8 + 4);
            float b[8] = {b0.x, b0.y, b0.z, b0.w, b1.x, b1.y, b1.z, b1.w};
            #pragma unroll
            for (int i = 0; i < 8; i++)
                #pragma unroll
                for (int j = 0; j < 8; j++)
                    acc[i][j] = fmaf(a[i], b[j], acc[i][j]);
        }
    }

    // bias + ELU, write H1 over buf (input tile fully consumed)
    __syncthreads();
    {
        float bj[8];
        #pragma unroll
        for (int j = 0; j < 8; j++) bj[j] = b1a[cg * 8 + j];
        #pragma unroll
        for (int i = 0; i < 8; i++) {
            float vv[8];
            #pragma unroll
            for (int j = 0; j < 8; j++) {
                float v = acc[i][j] + bj[j];
                vv[j] = (v > 0.f) ? v : expm1f(v);
                acc[i][j] = 0.f;
            }
            *(float4*)(buf + (er * 8 + i) * 256 + cg * 8)     = make_float4(vv[0], vv[1], vv[2], vv[3]);
            *(float4*)(buf + (er * 8 + i) * 256 + cg * 8 + 4) = make_float4(vv[4], vv[5], vv[6], vv[7]);
        }
    }

    // ---- GEMM2: H = H1(64x256) @ w1b(256x256) ----
    for (int k0 = 0; k0 < 256; k0 += 16) {
        __syncthreads();
        const float4* wsrc = (const float4*)(w1b + k0 * 256);
        float4* wd = (float4*)wbuf;
        #pragma unroll
        for (int t = 0; t < 4; t++) wd[tid + t * 256] = wsrc[tid + t * 256];
        __syncthreads();
        #pragma unroll
        for (int kk = 0; kk < 16; kk++) {
            float a[8];
            #pragma unroll
            for (int i = 0; i < 8; i++)
                a[i] = buf[(er * 8 + i) * 256 + k0 + kk];
            float4 b0 = *(float4*)(wbuf + kk * 256 + cg * 8);
            float4 b1 = *(float4*)(wbuf + kk * 256 + cg * 8 + 4);
            float b[8] = {b0.x, b0.y, b0.z, b0.w, b1.x, b1.y, b1.z, b1.w};
            #pragma unroll
            for (int i = 0; i < 8; i++)
                #pragma unroll
                for (int j = 0; j < 8; j++)
                    acc[i][j] = fmaf(a[i], b[j], acc[i][j]);
        }
    }

    // epilogue: bias + atomic scatter-add into g_sums[col[e]]
    {
        float bj[8];
        #pragma unroll
        for (int j = 0; j < 8; j++) bj[j] = b1b[cg * 8 + j];
        #pragma unroll
        for (int i = 0; i < 8; i++) {
            int c = scol[er * 8 + i];
            if (c >= 0) {
                float* dst = g_sums + (long long)c * 256 + cg * 8;
                #pragma unroll
                for (int j = 0; j < 8; j++)
                    atomicAdd(dst + j, acc[i][j] + bj[j]);
            }
        }
    }
}

// ======================================================================
// Kernel 2: node MLP (fused 2-layer), z = [x | mean] (64x384 tile)
// ======================================================================
__global__ __launch_bounds__(256)
void node_mlp_kernel(const float* __restrict__ x,
                     const float* __restrict__ w2a, const float* __restrict__ b2a,
                     const float* __restrict__ w2b, const float* __restrict__ b2b,
                     float* __restrict__ out, int N)
{
    extern __shared__ float smem[];
    float* buf  = smem;             // 64 * 384 (z tile; first 64*256 reused for H1)
    float* wbuf = smem + 64 * 384;  // 16 * 256
    __shared__ float sInv[64];

    const int tid = threadIdx.x;
    const int er  = tid >> 5;
    const int cg  = tid & 31;
    const int n0  = blockIdx.x * 64;
    const int ncnt = min(64, N - n0);

    if (tid < 64) {
        float inv = 0.f;
        if (tid < ncnt) {
            int c = g_cnt[n0 + tid];
            inv = 1.0f / (float)max(c, 1);
        }
        sInv[tid] = inv;
    }
    __syncthreads();

    // z[:, 0:128) = x
    for (int idx = tid; idx < 64 * 32; idx += 256) {
        int e = idx >> 5, c4 = idx & 31;
        float4 v = make_float4(0.f, 0.f, 0.f, 0.f);
        if (e < ncnt) v = *(const float4*)(x + (long long)(n0 + e) * 128 + c4 * 4);
        *(float4*)(buf + e * 384 + c4 * 4) = v;
    }
    // z[:, 128:384) = mean = sums * inv
    for (int idx = tid; idx < 64 * 64; idx += 256) {
        int e = idx >> 6, c4 = idx & 63;
        float4 v = make_float4(0.f, 0.f, 0.f, 0.f);
        if (e < ncnt) {
            v = *(const float4*)(g_sums + (long long)(n0 + e) * 256 + c4 * 4);
            float inv = sInv[e];
            v.x *= inv; v.y *= inv; v.z *= inv; v.w *= inv;
        }
        *(float4*)(buf + e * 384 + 128 + c4 * 4) = v;
    }

    float acc[8][8];
    #pragma unroll
    for (int i = 0; i < 8; i++)
        #pragma unroll
        for (int j = 0; j < 8; j++) acc[i][j] = 0.f;

    // ---- GEMM1: H1 = z(64x384) @ w2a(384x256) ----
    for (int k0 = 0; k0 < 384; k0 += 16) {
        __syncthreads();
        const float4* wsrc = (const float4*)(w2a + k0 * 256);
        float4* wd = (float4*)wbuf;
        #pragma unroll
        for (int t = 0; t < 4; t++) wd[tid + t * 256] = wsrc[tid + t * 256];
        __syncthreads();
        #pragma unroll
        for (int kk = 0; kk < 16; kk++) {
            float a[8];
            #pragma unroll
            for (int i = 0; i < 8; i++)
                a[i] = buf[(er * 8 + i) * 384 + k0 + kk];
            float4 b0 = *(float4*)(wbuf + kk * 256 + cg * 8);
            float4 b1 = *(float4*)(wbuf + kk * 256 + cg * 8 + 4);
            float b[8] = {b0.x, b0.y, b0.z, b0.w, b1.x, b1.y, b1.z, b1.w};
            #pragma unroll
            for (int i = 0; i < 8; i++)
                #pragma unroll
                for (int j = 0; j < 8; j++)
                    acc[i][j] = fmaf(a[i], b[j], acc[i][j]);
        }
    }

    // bias + ELU, write H1 (row stride 256) over buf
    __syncthreads();
    {
        float bj[8];
        #pragma unroll
        for (int j = 0; j < 8; j++) bj[j] = b2a[cg * 8 + j];
        #pragma unroll
        for (int i = 0; i < 8; i++) {
            float vv[8];
            #pragma unroll
            for (int j = 0; j < 8; j++) {
                float v = acc[i][j] + bj[j];
                vv[j] = (v > 0.f) ? v : expm1f(v);
                acc[i][j] = 0.f;
            }
            *(float4*)(buf + (er * 8 + i) * 256 + cg * 8)     = make_float4(vv[0], vv[1], vv[2], vv[3]);
            *(float4*)(buf + (er * 8 + i) * 256 + cg * 8 + 4) = make_float4(vv[4], vv[5], vv[6], vv[7]);
        }
    }

    // ---- GEMM2: out = H1(64x256) @ w2b(256x256) + b2b ----
    for (int k0 = 0; k0 < 256; k0 += 16) {
        __syncthreads();
        const float4* wsrc = (const float4*)(w2b + k0 * 256);
        float4* wd = (float4*)wbuf;
        #pragma unroll
        for (int t = 0; t < 4; t++) wd[tid + t * 256] = wsrc[tid + t * 256];
        __syncthreads();
        #pragma unroll
        for (int kk = 0; kk < 16; kk++) {
            float a[8];
            #pragma unroll
            for (int i = 0; i < 8; i++)
                a[i] = buf[(er * 8 + i) * 256 + k0 + kk];
            float4 b0 = *(float4*)(wbuf + kk * 256 + cg * 8);
            float4 b1 = *(float4*)(wbuf + kk * 256 + cg * 8 + 4);
            float b[8] = {b0.x, b0.y, b0.z, b0.w, b1.x, b1.y, b1.z, b1.w};
            #pragma unroll
            for (int i = 0; i < 8; i++)
                #pragma unroll
                for (int j = 0; j < 8; j++)
                    acc[i][j] = fmaf(a[i], b[j], acc[i][j]);
        }
    }

    {
        float bj[8];
        #pragma unroll
        for (int j = 0; j < 8; j++) bj[j] = b2b[cg * 8 + j];
        #pragma unroll
        for (int i = 0; i < 8; i++) {
            int n = n0 + er * 8 + i;
            if (n < N) {
                float vv[8];
                #pragma unroll
                for (int j = 0; j < 8; j++) vv[j] = acc[i][j] + bj[j];
                *(float4*)(out + (long long)n * 256 + cg * 8)     = make_float4(vv[0], vv[1], vv[2], vv[3]);
                *(float4*)(out + (long long)n * 256 + cg * 8 + 4) = make_float4(vv[4], vv[5], vv[6], vv[7]);
            }
        }
    }
}

// ======================================================================
// launch
// ======================================================================
extern "C" void kernel_launch(void* const* d_in, const int* in_sizes, int n_in,
                              void* d_out, int out_size)
{
    const float* x  = (const float*)d_in[0];
    const void*  ei = d_in[1];                 // int32 or int64 [2, E] — auto-detected
    const float* ea = (const float*)d_in[2];
    // d_in[3] = u (unused), d_in[4] = batch (unused)
    const float* w1a = (const float*)d_in[5];
    const float* b1a = (const float*)d_in[6];
    const float* w1b = (const float*)d_in[7];
    const float* b1b = (const float*)d_in[8];
    const float* w2a = (const float*)d_in[9];
    const float* b2a = (const float*)d_in[10];
    const float* w2b = (const float*)d_in[11];
    const float* b2b = (const float*)d_in[12];
    float* out = (float*)d_out;

    const int N = in_sizes[0] / 128;
    const int E = in_sizes[1] / 2;

    const int EDGE_SMEM = (64 * 256 + 16 * 256) * 4;  // 81920
    const int NODE_SMEM = (64 * 384 + 16 * 256) * 4;  // 114688
    cudaFuncSetAttribute(edge_mlp_kernel, cudaFuncAttributeMaxDynamicSharedMemorySize, EDGE_SMEM);
    cudaFuncSetAttribute(node_mlp_kernel, cudaFuncAttributeMaxDynamicSharedMemorySize, NODE_SMEM);

    detect_idx_kernel<<<1, 256>>>((const int*)ei);
    zero_kernel<<<1024, 256>>>(N);
    edge_mlp_kernel<<<(E + 63) / 64, 256, EDGE_SMEM>>>(x, ei, ea, w1a, b1a, w1b, b1b, E, N);
    node_mlp_kernel<<<(N + 63) / 64, 256, NODE_SMEM>>>(x, w2a, b2a, w2b, b2b, out, N);
}

// round 5
// speedup vs baseline: 1.1420x; 1.1420x over previous
#include <cuda_runtime.h>

// -------- problem constants --------
#define MAXN 50000   // N_NODES

// -------- scratch --------
__device__ float g_sums[MAXN * 256];
__device__ int   g_cnt [MAXN];
__device__ int   g_idx64;

// -------- f32x2 packed-math helpers (FFMA2 path, sm_100+) --------
typedef unsigned long long u64;

__device__ __forceinline__ u64 pack2(float lo, float hi) {
    u64 r; asm("mov.b64 %0, {%1, %2};" : "=l"(r) : "f"(lo), "f"(hi)); return r;
}
__device__ __forceinline__ u64 dup2(float v) {
    u64 r; asm("mov.b64 %0, {%1, %1};" : "=l"(r) : "f"(v)); return r;
}
__device__ __forceinline__ void fma2(u64& d, u64 a, u64 b) {
    asm("fma.rn.f32x2 %0, %1, %2, %0;" : "+l"(d) : "l"(a), "l"(b));
}
__device__ __forceinline__ void unpack2(u64 v, float& lo, float& hi) {
    asm("mov.b64 {%0, %1}, %2;" : "=f"(lo), "=f"(hi) : "l"(v));
}
__device__ __forceinline__ void red_add_v4(float* p, float a, float b, float c, float d) {
    asm volatile("red.global.add.v4.f32 [%0], {%1, %2, %3, %4};"
                 :: "l"(p), "f"(a), "f"(b), "f"(c), "f"(d) : "memory");
}

// ======================================================================
// Kernel -1: detect index dtype (int64 high words of idx<50000 are all 0)
// ======================================================================
__global__ void detect_idx_kernel(const int* __restrict__ ei_raw) {
    __shared__ int any_nonzero;
    if (threadIdx.x == 0) any_nonzero = 0;
    __syncthreads();
    for (int i = threadIdx.x; i < 1024; i += blockDim.x)
        if (ei_raw[2 * i + 1] != 0) any_nonzero = 1;
    __syncthreads();
    if (threadIdx.x == 0) g_idx64 = (any_nonzero == 0) ? 1 : 0;
}

__device__ __forceinline__ int load_idx(const void* ei, long long pos, int nmax) {
    int v = g_idx64 ? (int)((const long long*)ei)[pos]
                    : ((const int*)ei)[pos];
    return min(max(v, 0), nmax - 1);
}

// ======================================================================
// Kernel 0: zero scratch
// ======================================================================
__global__ void zero_kernel(int n_nodes) {
    int tid    = blockIdx.x * blockDim.x + threadIdx.x;
    int stride = gridDim.x * blockDim.x;
    int tot4 = n_nodes * 64;
    float4* s4 = (float4*)g_sums;
    float4 z = make_float4(0.f, 0.f, 0.f, 0.f);
    for (int i = tid; i < tot4; i += stride) s4[i] = z;
    for (int i = tid; i < n_nodes; i += stride) g_cnt[i] = 0;
}

// ---- shared inner-product step: 8 rows x 8 cols, packed as 8x4 f32x2 ----
// acc[i][j] += a_row[i] * b[j]   (b loaded as 2x ulonglong2 from wbuf)
#define GEMM_KK_STEP(BUF, STRIDE, K)                                       \
    {                                                                      \
        u64 a2[8];                                                         \
        _Pragma("unroll")                                                  \
        for (int i = 0; i < 8; i++)                                        \
            a2[i] = dup2(BUF[(er * 8 + i) * STRIDE + (K)]);                \
        ulonglong2 bb0 = *(const ulonglong2*)(wbuf + kk * 256 + cg * 8);   \
        ulonglong2 bb1 = *(const ulonglong2*)(wbuf + kk * 256 + cg * 8 + 4);\
        _Pragma("unroll")                                                  \
        for (int i = 0; i < 8; i++) {                                      \
            fma2(acc2[i][0], a2[i], bb0.x);                                \
            fma2(acc2[i][1], a2[i], bb0.y);                                \
            fma2(acc2[i][2], a2[i], bb1.x);                                \
            fma2(acc2[i][3], a2[i], bb1.y);                                \
        }                                                                  \
    }

// ======================================================================
// Kernel 1: edge MLP (fused 2-layer, f32x2) + vector-atomic scatter
// ======================================================================
__global__ __launch_bounds__(256, 2)
void edge_mlp_kernel(const float* __restrict__ x,
                     const void* __restrict__ edge_index,
                     const float* __restrict__ edge_attr,
                     const float* __restrict__ w1a, const float* __restrict__ b1a,
                     const float* __restrict__ w1b, const float* __restrict__ b1b,
                     int E, int N)
{
    extern __shared__ float smem[];
    float* buf  = smem;             // 64 * 256
    float* wbuf = smem + 64 * 256;  // 16 * 256
    __shared__ int srow[64];
    __shared__ int scol[64];

    const int tid = threadIdx.x;
    const int er  = tid >> 5;
    const int cg  = tid & 31;
    const int e0  = blockIdx.x * 64;
    const int ecnt = min(64, E - e0);

    if (tid < 64) {
        int r = -1, c = -1;
        if (tid < ecnt) {
            r = load_idx(edge_index, (long long)(e0 + tid), N);
            c = load_idx(edge_index, (long long)E + e0 + tid, N);
            atomicAdd(&g_cnt[c], 1);
        }
        srow[tid] = r;
        scol[tid] = c;
    }
    __syncthreads();

    for (int idx = tid; idx < 64 * 32; idx += 256) {
        int e = idx >> 5, c4 = idx & 31;
        float4 v = make_float4(0.f, 0.f, 0.f, 0.f);
        if (e < ecnt) {
            long long r = srow[e];
            v = *(const float4*)(x + r * 128 + c4 * 4);
        }
        *(float4*)(buf + e * 256 + c4 * 4) = v;
    }
    for (int idx = tid; idx < 64 * 32; idx += 256) {
        int e = idx >> 5, c4 = idx & 31;
        float4 v = make_float4(0.f, 0.f, 0.f, 0.f);
        if (e < ecnt)
            v = *(const float4*)(edge_attr + (long long)(e0 + e) * 128 + c4 * 4);
        *(float4*)(buf + e * 256 + 128 + c4 * 4) = v;
    }

    u64 acc2[8][4];
    #pragma unroll
    for (int i = 0; i < 8; i++)
        #pragma unroll
        for (int j = 0; j < 4; j++) acc2[i][j] = 0ULL;

    // ---- GEMM1: H1 = buf(64x256) @ w1a ----
    for (int k0 = 0; k0 < 256; k0 += 16) {
        __syncthreads();
        const float4* wsrc = (const float4*)(w1a + k0 * 256);
        float4* wd = (float4*)wbuf;
        #pragma unroll
        for (int t = 0; t < 4; t++) wd[tid + t * 256] = wsrc[tid + t * 256];
        __syncthreads();
        #pragma unroll
        for (int kk = 0; kk < 16; kk++)
            GEMM_KK_STEP(buf, 256, k0 + kk)
    }

    // bias + ELU -> overwrite buf
    __syncthreads();
    {
        float bj[8];
        #pragma unroll
        for (int j = 0; j < 8; j++) bj[j] = b1a[cg * 8 + j];
        #pragma unroll
        for (int i = 0; i < 8; i++) {
            float vv[8];
            #pragma unroll
            for (int j = 0; j < 4; j++) {
                float lo, hi;
                unpack2(acc2[i][j], lo, hi);
                acc2[i][j] = 0ULL;
                float v0 = lo + bj[2 * j],     v1 = hi + bj[2 * j + 1];
                vv[2 * j]     = (v0 > 0.f) ? v0 : expm1f(v0);
                vv[2 * j + 1] = (v1 > 0.f) ? v1 : expm1f(v1);
            }
            *(float4*)(buf + (er * 8 + i) * 256 + cg * 8)     = make_float4(vv[0], vv[1], vv[2], vv[3]);
            *(float4*)(buf + (er * 8 + i) * 256 + cg * 8 + 4) = make_float4(vv[4], vv[5], vv[6], vv[7]);
        }
    }

    // ---- GEMM2: H = H1(64x256) @ w1b ----
    for (int k0 = 0; k0 < 256; k0 += 16) {
        __syncthreads();
        const float4* wsrc = (const float4*)(w1b + k0 * 256);
        float4* wd = (float4*)wbuf;
        #pragma unroll
        for (int t = 0; t < 4; t++) wd[tid + t * 256] = wsrc[tid + t * 256];
        __syncthreads();
        #pragma unroll
        for (int kk = 0; kk < 16; kk++)
            GEMM_KK_STEP(buf, 256, k0 + kk)
    }

    // epilogue: bias + vector-atomic scatter-add
    {
        float bj[8];
        #pragma unroll
        for (int j = 0; j < 8; j++) bj[j] = b1b[cg * 8 + j];
        #pragma unroll
        for (int i = 0; i < 8; i++) {
            int c = scol[er * 8 + i];
            if (c >= 0) {
                float vv[8];
                #pragma unroll
                for (int j = 0; j < 4; j++) {
                    float lo, hi;
                    unpack2(acc2[i][j], lo, hi);
                    vv[2 * j]     = lo + bj[2 * j];
                    vv[2 * j + 1] = hi + bj[2 * j + 1];
                }
                float* dst = g_sums + (long long)c * 256 + cg * 8;
                red_add_v4(dst,     vv[0], vv[1], vv[2], vv[3]);
                red_add_v4(dst + 4, vv[4], vv[5], vv[6], vv[7]);
            }
        }
    }
}

// ======================================================================
// Kernel 2: node MLP (fused 2-layer, f32x2)
// ======================================================================
__global__ __launch_bounds__(256)
void node_mlp_kernel(const float* __restrict__ x,
                     const float* __restrict__ w2a, const float* __restrict__ b2a,
                     const float* __restrict__ w2b, const float* __restrict__ b2b,
                     float* __restrict__ out, int N)
{
    extern __shared__ float smem[];
    float* buf  = smem;             // 64 * 384
    float* wbuf = smem + 64 * 384;  // 16 * 256
    __shared__ float sInv[64];

    const int tid = threadIdx.x;
    const int er  = tid >> 5;
    const int cg  = tid & 31;
    const int n0  = blockIdx.x * 64;
    const int ncnt = min(64, N - n0);

    if (tid < 64) {
        float inv = 0.f;
        if (tid < ncnt) {
            int c = g_cnt[n0 + tid];
            inv = 1.0f / (float)max(c, 1);
        }
        sInv[tid] = inv;
    }
    __syncthreads();

    for (int idx = tid; idx < 64 * 32; idx += 256) {
        int e = idx >> 5, c4 = idx & 31;
        float4 v = make_float4(0.f, 0.f, 0.f, 0.f);
        if (e < ncnt) v = *(const float4*)(x + (long long)(n0 + e) * 128 + c4 * 4);
        *(float4*)(buf + e * 384 + c4 * 4) = v;
    }
    for (int idx = tid; idx < 64 * 64; idx += 256) {
        int e = idx >> 6, c4 = idx & 63;
        float4 v = make_float4(0.f, 0.f, 0.f, 0.f);
        if (e < ncnt) {
            v = *(const float4*)(g_sums + (long long)(n0 + e) * 256 + c4 * 4);
            float inv = sInv[e];
            v.x *= inv; v.y *= inv; v.z *= inv; v.w *= inv;
        }
        *(float4*)(buf + e * 384 + 128 + c4 * 4) = v;
    }

    u64 acc2[8][4];
    #pragma unroll
    for (int i = 0; i < 8; i++)
        #pragma unroll
        for (int j = 0; j < 4; j++) acc2[i][j] = 0ULL;

    // ---- GEMM1: H1 = z(64x384) @ w2a ----
    for (int k0 = 0; k0 < 384; k0 += 16) {
        __syncthreads();
        const float4* wsrc = (const float4*)(w2a + k0 * 256);
        float4* wd = (float4*)wbuf;
        #pragma unroll
        for (int t = 0; t < 4; t++) wd[tid + t * 256] = wsrc[tid + t * 256];
        __syncthreads();
        #pragma unroll
        for (int kk = 0; kk < 16; kk++)
            GEMM_KK_STEP(buf, 384, k0 + kk)
    }

    // bias + ELU -> write H1 (stride 256) over buf
    __syncthreads();
    {
        float bj[8];
        #pragma unroll
        for (int j = 0; j < 8; j++) bj[j] = b2a[cg * 8 + j];
        #pragma unroll
        for (int i = 0; i < 8; i++) {
            float vv[8];
            #pragma unroll
            for (int j = 0; j < 4; j++) {
                float lo, hi;
                unpack2(acc2[i][j], lo, hi);
                acc2[i][j] = 0ULL;
                float v0 = lo + bj[2 * j],     v1 = hi + bj[2 * j + 1];
                vv[2 * j]     = (v0 > 0.f) ? v0 : expm1f(v0);
                vv[2 * j + 1] = (v1 > 0.f) ? v1 : expm1f(v1);
            }
            *(float4*)(buf + (er * 8 + i) * 256 + cg * 8)     = make_float4(vv[0], vv[1], vv[2], vv[3]);
            *(float4*)(buf + (er * 8 + i) * 256 + cg * 8 + 4) = make_float4(vv[4], vv[5], vv[6], vv[7]);
        }
    }

    // ---- GEMM2: out = H1(64x256) @ w2b + b2b ----
    for (int k0 = 0; k0 < 256; k0 += 16) {
        __syncthreads();
        const float4* wsrc = (const float4*)(w2b + k0 * 256);
        float4* wd = (float4*)wbuf;
        #pragma unroll
        for (int t = 0; t < 4; t++) wd[tid + t * 256] = wsrc[tid + t * 256];
        __syncthreads();
        #pragma unroll
        for (int kk = 0; kk < 16; kk++)
            GEMM_KK_STEP(buf, 256, k0 + kk)
    }

    {
        float bj[8];
        #pragma unroll
        for (int j = 0; j < 8; j++) bj[j] = b2b[cg * 8 + j];
        #pragma unroll
        for (int i = 0; i < 8; i++) {
            int n = n0 + er * 8 + i;
            if (n < N) {
                float vv[8];
                #pragma unroll
                for (int j = 0; j < 4; j++) {
                    float lo, hi;
                    unpack2(acc2[i][j], lo, hi);
                    vv[2 * j]     = lo + bj[2 * j];
                    vv[2 * j + 1] = hi + bj[2 * j + 1];
                }
                *(float4*)(out + (long long)n * 256 + cg * 8)     = make_float4(vv[0], vv[1], vv[2], vv[3]);
                *(float4*)(out + (long long)n * 256 + cg * 8 + 4) = make_float4(vv[4], vv[5], vv[6], vv[7]);
            }
        }
    }
}

// ======================================================================
// launch
// ======================================================================
extern "C" void kernel_launch(void* const* d_in, const int* in_sizes, int n_in,
                              void* d_out, int out_size)
{
    const float* x  = (const float*)d_in[0];
    const void*  ei = d_in[1];
    const float* ea = (const float*)d_in[2];
    const float* w1a = (const float*)d_in[5];
    const float* b1a = (const float*)d_in[6];
    const float* w1b = (const float*)d_in[7];
    const float* b1b = (const float*)d_in[8];
    const float* w2a = (const float*)d_in[9];
    const float* b2a = (const float*)d_in[10];
    const float* w2b = (const float*)d_in[11];
    const float* b2b = (const float*)d_in[12];
    float* out = (float*)d_out;

    const int N = in_sizes[0] / 128;
    const int E = in_sizes[1] / 2;

    const int EDGE_SMEM = (64 * 256 + 16 * 256) * 4;  // 81920
    const int NODE_SMEM = (64 * 384 + 16 * 256) * 4;  // 114688
    cudaFuncSetAttribute(edge_mlp_kernel, cudaFuncAttributeMaxDynamicSharedMemorySize, EDGE_SMEM);
    cudaFuncSetAttribute(node_mlp_kernel, cudaFuncAttributeMaxDynamicSharedMemorySize, NODE_SMEM);

    detect_idx_kernel<<<1, 256>>>((const int*)ei);
    zero_kernel<<<1024, 256>>>(N);
    edge_mlp_kernel<<<(E + 63) / 64, 256, EDGE_SMEM>>>(x, ei, ea, w1a, b1a, w1b, b1b, E, N);
    node_mlp_kernel<<<(N + 63) / 64, 256, NODE_SMEM>>>(x, w2a, b2a, w2b, b2b, out, N);
}

// round 9
// speedup vs baseline: 2.1850x; 1.9134x over previous
#include <cuda_runtime.h>
#include <cuda_bf16.h>
#include <cstdint>

// ---------------- problem constants ----------------
#define MAXN 50000

// ---------------- device scratch ----------------
__device__ float g_sums[MAXN * 256];
__device__ int   g_cnt [MAXN];
__device__ int   g_idx64;
// weight blobs: per layer 8 chunks (k=32) x [hi 20480 | lo 20480] = 327680 B
// layout inside half-chunk: [n (256)][stride 80 B], element (n, kk) at n*80 + kk*2
__device__ __align__(16) unsigned char g_w1blob[8 * 40960];
__device__ __align__(16) unsigned char g_w2blob[8 * 40960];

// ---------------- smem layout (bytes) ----------------
#define A_STRIDE_B 528              // 264 halves per row (256 + 8 pad)
#define SA_HI  0
#define SA_LO  67584                // 128 * 528
#define SB0    135168
#define SB1    176128               // SB0 + 40960
#define SBIA   217088               // b1a, 256 floats
#define SBIB   218112               // b1b, 256 floats
#define SROW   219136               // 128 ints
#define SCOL   219648
#define EDGE_SMEM 220160

#define CHUNK_BYTES 40960
#define CHUNK_HALF  20480

// ---------------- helpers ----------------
__device__ __forceinline__ uint32_t smem_u32(const void* p) {
    uint32_t a;
    asm("{ .reg .u64 t; cvta.to.shared.u64 t, %1; cvt.u32.u64 %0, t; }" : "=r"(a) : "l"(p));
    return a;
}
__device__ __forceinline__ void cp16(uint32_t saddr, const void* gaddr) {
    asm volatile("cp.async.cg.shared.global [%0], [%1], 16;" :: "r"(saddr), "l"(gaddr));
}
#define CP_COMMIT() asm volatile("cp.async.commit_group;")
#define CP_WAIT1()  asm volatile("cp.async.wait_group 1;")

__device__ __forceinline__ void red_add_v2(float* p, float a, float b) {
    asm volatile("red.global.add.v2.f32 [%0], {%1, %2};" :: "l"(p), "f"(a), "f"(b) : "memory");
}
__device__ __forceinline__ void mma16816(float* c, const uint32_t* a, const uint32_t* b) {
    asm volatile(
        "mma.sync.aligned.m16n8k16.row.col.f32.bf16.bf16.f32 "
        "{%0,%1,%2,%3}, {%4,%5,%6,%7}, {%8,%9}, {%0,%1,%2,%3};"
        : "+f"(c[0]), "+f"(c[1]), "+f"(c[2]), "+f"(c[3])
        : "r"(a[0]), "r"(a[1]), "r"(a[2]), "r"(a[3]), "r"(b[0]), "r"(b[1]));
}
// split two fp32 into packed bf16x2 (hi) and bf16x2 (lo residual)
__device__ __forceinline__ void split2(float v0, float v1, uint32_t& hi, uint32_t& lo) {
    __nv_bfloat16 h0 = __float2bfloat16(v0), h1 = __float2bfloat16(v1);
    __nv_bfloat162 hh{h0, h1};
    __nv_bfloat162 ll{__float2bfloat16(v0 - __bfloat162float(h0)),
                      __float2bfloat16(v1 - __bfloat162float(h1))};
    hi = *(uint32_t*)&hh;
    lo = *(uint32_t*)&ll;
}

// ======================================================================
// detect index dtype (int64 high words of idx<50000 are all zero)
// ======================================================================
__global__ void detect_idx_kernel(const int* __restrict__ ei_raw) {
    __shared__ int any_nonzero;
    if (threadIdx.x == 0) any_nonzero = 0;
    __syncthreads();
    for (int i = threadIdx.x; i < 1024; i += blockDim.x)
        if (ei_raw[2 * i + 1] != 0) any_nonzero = 1;
    __syncthreads();
    if (threadIdx.x == 0) g_idx64 = (any_nonzero == 0) ? 1 : 0;
}
__device__ __forceinline__ int load_idx(const void* ei, long long pos, int nmax) {
    int v = g_idx64 ? (int)((const long long*)ei)[pos] : ((const int*)ei)[pos];
    return min(max(v, 0), nmax - 1);
}

// ======================================================================
// zero scratch
// ======================================================================
__global__ void zero_kernel(int n_nodes) {
    int tid = blockIdx.x * blockDim.x + threadIdx.x;
    int stride = gridDim.x * blockDim.x;
    int tot4 = n_nodes * 64;
    float4* s4 = (float4*)g_sums;
    float4 z = make_float4(0.f, 0.f, 0.f, 0.f);
    for (int i = tid; i < tot4; i += stride) s4[i] = z;
    for (int i = tid; i < n_nodes; i += stride) g_cnt[i] = 0;
}

// ======================================================================
// prep: w [256 K][256 N] fp32 -> blob chunks: ch = k>>5, kk = k&31
//   hi at ch*40960 + n*80 + kk*2 ; lo at +20480   (B^T, padded rows)
// ======================================================================
__global__ void prep_weights_kernel(const float* __restrict__ w, unsigned char* __restrict__ blob) {
    int idx = blockIdx.x * blockDim.x + threadIdx.x;
    if (idx >= 256 * 256) return;
    int k = idx >> 8, n = idx & 255;
    float v = w[idx];
    __nv_bfloat16 hi = __float2bfloat16(v);
    __nv_bfloat16 lo = __float2bfloat16(v - __bfloat162float(hi));
    int ch = k >> 5, kk = k & 31;
    unsigned char* base = blob + ch * CHUNK_BYTES + n * 80 + kk * 2;
    *(__nv_bfloat16*)(base)              = hi;
    *(__nv_bfloat16*)(base + CHUNK_HALF) = lo;
}

// ======================================================================
// edge kernel: HMMA bf16-3split, 128 edges / CTA, 512 threads (16 warps)
// ======================================================================
__global__ __launch_bounds__(512, 1)
void edge_mma_kernel(const float* __restrict__ x,
                     const void* __restrict__ edge_index,
                     const float* __restrict__ edge_attr,
                     const float* __restrict__ b1a, const float* __restrict__ b1b,
                     int E, int N)
{
    extern __shared__ __align__(16) unsigned char smem[];
    const uint32_t sbase = smem_u32(smem);
    const int tid  = threadIdx.x;
    const int lane = tid & 31;
    const int w    = tid >> 5;          // 16 warps
    const int g    = lane >> 2;         // 0..7
    const int tg   = lane & 3;          // 0..3
    const int mb   = (w >> 2) * 32;     // warp M base (0/32/64/96)
    const int nb   = (w & 3) * 64;      // warp N base (0/64/128/192)

    const int e0 = blockIdx.x * 128;
    const int ecnt = min(128, E - e0);
    int*   srow = (int*)(smem + SROW);
    int*   scol = (int*)(smem + SCOL);
    float* sba  = (float*)(smem + SBIA);
    float* sbb  = (float*)(smem + SBIB);

    if (tid < 128) {
        int r = -1, c = -1;
        if (tid < ecnt) {
            r = load_idx(edge_index, (long long)(e0 + tid), N);
            c = load_idx(edge_index, (long long)E + e0 + tid, N);
            atomicAdd(&g_cnt[c], 1);
        }
        srow[tid] = r;
        scol[tid] = c;
    }
    if (tid < 256) {
        sba[tid] = b1a[tid];
        sbb[tid] = b1b[tid];
    }
    __syncthreads();

    // ---- gather inputs, split, store to A_hi/A_lo (padded rows) ----
    for (int idx = tid; idx < 128 * 32; idx += 512) {       // x : k = c4*4
        int e = idx >> 5, c4 = idx & 31;
        float4 v = make_float4(0.f, 0.f, 0.f, 0.f);
        if (e < ecnt) v = *(const float4*)(x + (long long)srow[e] * 128 + c4 * 4);
        uint32_t h0, l0, h1, l1;
        split2(v.x, v.y, h0, l0);
        split2(v.z, v.w, h1, l1);
        uint32_t off = (uint32_t)e * A_STRIDE_B + (uint32_t)c4 * 8;
        *(uint2*)(smem + SA_HI + off) = make_uint2(h0, h1);
        *(uint2*)(smem + SA_LO + off) = make_uint2(l0, l1);
    }
    for (int idx = tid; idx < 128 * 32; idx += 512) {       // edge_attr : k = 128 + c4*4
        int e = idx >> 5, c4 = idx & 31;
        float4 v = make_float4(0.f, 0.f, 0.f, 0.f);
        if (e < ecnt) v = *(const float4*)(edge_attr + (long long)(e0 + e) * 128 + c4 * 4);
        uint32_t h0, l0, h1, l1;
        split2(v.x, v.y, h0, l0);
        split2(v.z, v.w, h1, l1);
        uint32_t off = (uint32_t)e * A_STRIDE_B + 256u + (uint32_t)c4 * 8;
        *(uint2*)(smem + SA_HI + off) = make_uint2(h0, h1);
        *(uint2*)(smem + SA_LO + off) = make_uint2(l0, l1);
    }
    __syncthreads();

    float acc[2][8][4];
    #pragma unroll
    for (int mt = 0; mt < 2; mt++)
        #pragma unroll
        for (int nt = 0; nt < 8; nt++)
            #pragma unroll
            for (int i = 0; i < 4; i++) acc[mt][nt][i] = 0.f;

    // chunk copy: 2560 x 16B with 512 threads (5 each)
    #define CP_CHUNK(GSRC, SDST)                                           \
        {                                                                  \
            const unsigned char* _g = (GSRC);                              \
            uint32_t _s = sbase + (SDST);                                  \
            _Pragma("unroll")                                              \
            for (int _j = 0; _j < 5; _j++)                                 \
                cp16(_s + (tid + _j * 512) * 16, _g + (tid + _j * 512) * 16); \
        }

    // one k-step (k16) of the 3-split GEMM on current B buffer
    #define GEMM_KSTEP(K0, KC, SBCUR)                                      \
        {                                                                  \
            uint32_t ahi[2][4], alo[2][4];                                 \
            _Pragma("unroll")                                              \
            for (int mt = 0; mt < 2; mt++) {                               \
                uint32_t r0 = (uint32_t)(mb + mt * 16 + g);                \
                uint32_t o0 = r0 * A_STRIDE_B + (uint32_t)((K0) + tg * 2) * 2; \
                uint32_t o1 = o0 + 8 * A_STRIDE_B;                         \
                ahi[mt][0] = *(uint32_t*)(smem + SA_HI + o0);              \
                ahi[mt][1] = *(uint32_t*)(smem + SA_HI + o1);              \
                ahi[mt][2] = *(uint32_t*)(smem + SA_HI + o0 + 16);         \
                ahi[mt][3] = *(uint32_t*)(smem + SA_HI + o1 + 16);         \
                alo[mt][0] = *(uint32_t*)(smem + SA_LO + o0);              \
                alo[mt][1] = *(uint32_t*)(smem + SA_LO + o1);              \
                alo[mt][2] = *(uint32_t*)(smem + SA_LO + o0 + 16);         \
                alo[mt][3] = *(uint32_t*)(smem + SA_LO + o1 + 16);         \
            }                                                              \
            _Pragma("unroll")                                              \
            for (int nt = 0; nt < 8; nt++) {                               \
                uint32_t n = (uint32_t)(nb + nt * 8 + g);                  \
                uint32_t bo = n * 80 + (uint32_t)((KC) + tg * 2) * 2;      \
                uint32_t bhi[2], blo[2];                                   \
                bhi[0] = *(uint32_t*)(smem + (SBCUR) + bo);                \
                bhi[1] = *(uint32_t*)(smem + (SBCUR) + bo + 16);           \
                blo[0] = *(uint32_t*)(smem + (SBCUR) + CHUNK_HALF + bo);   \
                blo[1] = *(uint32_t*)(smem + (SBCUR) + CHUNK_HALF + bo + 16); \
                _Pragma("unroll")                                          \
                for (int mt = 0; mt < 2; mt++) {                           \
                    mma16816(acc[mt][nt], ahi[mt], bhi);                   \
                    mma16816(acc[mt][nt], ahi[mt], blo);                   \
                    mma16816(acc[mt][nt], alo[mt], bhi);                   \
                }                                                          \
            }                                                              \
        }

    // ---- GEMM1: [x|ea] (128x256) @ w1a -> acc ----
    CP_CHUNK(g_w1blob, SB0);
    CP_COMMIT();
    for (int ch = 0; ch < 8; ch++) {
        if (ch < 7) { CP_CHUNK(g_w1blob + (ch + 1) * CHUNK_BYTES, ((ch + 1) & 1) ? SB1 : SB0); }
        else        { CP_CHUNK(g_w2blob, SB0); }    // prefetch GEMM2 chunk 0
        CP_COMMIT();
        CP_WAIT1();
        __syncthreads();
        uint32_t sb = (ch & 1) ? SB1 : SB0;
        GEMM_KSTEP(ch * 32,      0,  sb);
        GEMM_KSTEP(ch * 32 + 16, 16, sb);
        __syncthreads();
    }

    // ---- layer-1 epilogue: bias + ELU + re-split -> overwrite A ----
    {
        #pragma unroll
        for (int mt = 0; mt < 2; mt++) {
            uint32_t r0 = (uint32_t)(mb + mt * 16 + g);
            #pragma unroll
            for (int nt = 0; nt < 8; nt++) {
                int cb = nb + nt * 8 + tg * 2;
                float b0 = sba[cb], b1 = sba[cb + 1];
                float v00 = acc[mt][nt][0] + b0, v01 = acc[mt][nt][1] + b1;
                float v10 = acc[mt][nt][2] + b0, v11 = acc[mt][nt][3] + b1;
                v00 = (v00 > 0.f) ? v00 : expm1f(v00);
                v01 = (v01 > 0.f) ? v01 : expm1f(v01);
                v10 = (v10 > 0.f) ? v10 : expm1f(v10);
                v11 = (v11 > 0.f) ? v11 : expm1f(v11);
                uint32_t hi, lo;
                uint32_t o = r0 * A_STRIDE_B + (uint32_t)cb * 2;
                split2(v00, v01, hi, lo);
                *(uint32_t*)(smem + SA_HI + o) = hi;
                *(uint32_t*)(smem + SA_LO + o) = lo;
                o += 8 * A_STRIDE_B;
                split2(v10, v11, hi, lo);
                *(uint32_t*)(smem + SA_HI + o) = hi;
                *(uint32_t*)(smem + SA_LO + o) = lo;
                acc[mt][nt][0] = 0.f; acc[mt][nt][1] = 0.f;
                acc[mt][nt][2] = 0.f; acc[mt][nt][3] = 0.f;
            }
        }
    }
    __syncthreads();

    // ---- GEMM2: elu(H1) (128x256) @ w1b -> acc ----
    for (int ch = 0; ch < 8; ch++) {
        if (ch < 7) { CP_CHUNK(g_w2blob + (ch + 1) * CHUNK_BYTES, ((ch + 1) & 1) ? SB1 : SB0); }
        CP_COMMIT();            // empty group on last iter keeps accounting uniform
        CP_WAIT1();
        __syncthreads();
        uint32_t sb = (ch & 1) ? SB1 : SB0;
        GEMM_KSTEP(ch * 32,      0,  sb);
        GEMM_KSTEP(ch * 32 + 16, 16, sb);
        __syncthreads();
    }

    // ---- scatter epilogue: + b1b, red.global.add.v2 into g_sums ----
    {
        #pragma unroll
        for (int mt = 0; mt < 2; mt++) {
            int er0 = mb + mt * 16 + g;
            int c0 = scol[er0];
            int c1 = scol[er0 + 8];
            float* p0 = (c0 >= 0) ? (g_sums + (long long)c0 * 256) : nullptr;
            float* p1 = (c1 >= 0) ? (g_sums + (long long)c1 * 256) : nullptr;
            #pragma unroll
            for (int nt = 0; nt < 8; nt++) {
                int cb = nb + nt * 8 + tg * 2;
                float b0 = sbb[cb], b1 = sbb[cb + 1];
                if (p0) red_add_v2(p0 + cb, acc[mt][nt][0] + b0, acc[mt][nt][1] + b1);
                if (p1) red_add_v2(p1 + cb, acc[mt][nt][2] + b0, acc[mt][nt][3] + b1);
            }
        }
    }
}

// ======================================================================
// node MLP (R4 scalar fp32 version)
// ======================================================================
__global__ __launch_bounds__(256)
void node_mlp_kernel(const float* __restrict__ x,
                     const float* __restrict__ w2a, const float* __restrict__ b2a,
                     const float* __restrict__ w2b, const float* __restrict__ b2b,
                     float* __restrict__ out, int N)
{
    extern __shared__ float smemf[];
    float* buf  = smemf;             // 64*384
    float* wbuf = smemf + 64 * 384;  // 16*256
    __shared__ float sInv[64];

    const int tid = threadIdx.x;
    const int er  = tid >> 5;
    const int cg  = tid & 31;
    const int n0  = blockIdx.x * 64;
    const int ncnt = min(64, N - n0);

    if (tid < 64) {
        float inv = 0.f;
        if (tid < ncnt) inv = 1.0f / (float)max(g_cnt[n0 + tid], 1);
        sInv[tid] = inv;
    }
    __syncthreads();

    for (int idx = tid; idx < 64 * 32; idx += 256) {
        int e = idx >> 5, c4 = idx & 31;
        float4 v = make_float4(0.f, 0.f, 0.f, 0.f);
        if (e < ncnt) v = *(const float4*)(x + (long long)(n0 + e) * 128 + c4 * 4);
        *(float4*)(buf + e * 384 + c4 * 4) = v;
    }
    for (int idx = tid; idx < 64 * 64; idx += 256) {
        int e = idx >> 6, c4 = idx & 63;
        float4 v = make_float4(0.f, 0.f, 0.f, 0.f);
        if (e < ncnt) {
            v = *(const float4*)(g_sums + (long long)(n0 + e) * 256 + c4 * 4);
            float inv = sInv[e];
            v.x *= inv; v.y *= inv; v.z *= inv; v.w *= inv;
        }
        *(float4*)(buf + e * 384 + 128 + c4 * 4) = v;
    }

    float acc[8][8];
    #pragma unroll
    for (int i = 0; i < 8; i++)
        #pragma unroll
        for (int j = 0; j < 8; j++) acc[i][j] = 0.f;

    for (int k0 = 0; k0 < 384; k0 += 16) {
        __syncthreads();
        const float4* wsrc = (const float4*)(w2a + k0 * 256);
        float4* wd = (float4*)wbuf;
        #pragma unroll
        for (int t = 0; t < 4; t++) wd[tid + t * 256] = wsrc[tid + t * 256];
        __syncthreads();
        #pragma unroll
        for (int kk = 0; kk < 16; kk++) {
            float a[8];
            #pragma unroll
            for (int i = 0; i < 8; i++) a[i] = buf[(er * 8 + i) * 384 + k0 + kk];
            float4 b0 = *(float4*)(wbuf + kk * 256 + cg * 8);
            float4 b1 = *(float4*)(wbuf + kk * 256 + cg * 8 + 4);
            float b[8] = {b0.x, b0.y, b0.z, b0.w, b1.x, b1.y, b1.z, b1.w};
            #pragma unroll
            for (int i = 0; i < 8; i++)
                #pragma unroll
                for (int j = 0; j < 8; j++) acc[i][j] = fmaf(a[i], b[j], acc[i][j]);
        }
    }

    __syncthreads();
    {
        float bj[8];
        #pragma unroll
        for (int j = 0; j < 8; j++) bj[j] = b2a[cg * 8 + j];
        #pragma unroll
        for (int i = 0; i < 8; i++) {
            float vv[8];
            #pragma unroll
            for (int j = 0; j < 8; j++) {
                float v = acc[i][j] + bj[j];
                vv[j] = (v > 0.f) ? v : expm1f(v);
                acc[i][j] = 0.f;
            }
            *(float4*)(buf + (er * 8 + i) * 256 + cg * 8)     = make_float4(vv[0], vv[1], vv[2], vv[3]);
            *(float4*)(buf + (er * 8 + i) * 256 + cg * 8 + 4) = make_float4(vv[4], vv[5], vv[6], vv[7]);
        }
    }

    for (int k0 = 0; k0 < 256; k0 += 16) {
        __syncthreads();
        const float4* wsrc = (const float4*)(w2b + k0 * 256);
        float4* wd = (float4*)wbuf;
        #pragma unroll
        for (int t = 0; t < 4; t++) wd[tid + t * 256] = wsrc[tid + t * 256];
        __syncthreads();
        #pragma unroll
        for (int kk = 0; kk < 16; kk++) {
            float a[8];
            #pragma unroll
            for (int i = 0; i < 8; i++) a[i] = buf[(er * 8 + i) * 256 + k0 + kk];
            float4 b0 = *(float4*)(wbuf + kk * 256 + cg * 8);
            float4 b1 = *(float4*)(wbuf + kk * 256 + cg * 8 + 4);
            float b[8] = {b0.x, b0.y, b0.z, b0.w, b1.x, b1.y, b1.z, b1.w};
            #pragma unroll
            for (int i = 0; i < 8; i++)
                #pragma unroll
                for (int j = 0; j < 8; j++) acc[i][j] = fmaf(a[i], b[j], acc[i][j]);
        }
    }

    {
        float bj[8];
        #pragma unroll
        for (int j = 0; j < 8; j++) bj[j] = b2b[cg * 8 + j];
        #pragma unroll
        for (int i = 0; i < 8; i++) {
            int n = n0 + er * 8 + i;
            if (n < N) {
                float vv[8];
                #pragma unroll
                for (int j = 0; j < 8; j++) vv[j] = acc[i][j] + bj[j];
                *(float4*)(out + (long long)n * 256 + cg * 8)     = make_float4(vv[0], vv[1], vv[2], vv[3]);
                *(float4*)(out + (long long)n * 256 + cg * 8 + 4) = make_float4(vv[4], vv[5], vv[6], vv[7]);
            }
        }
    }
}

// ======================================================================
// launch
// ======================================================================
extern "C" void kernel_launch(void* const* d_in, const int* in_sizes, int n_in,
                              void* d_out, int out_size)
{
    const float* x  = (const float*)d_in[0];
    const void*  ei = d_in[1];
    const float* ea = (const float*)d_in[2];
    const float* w1a = (const float*)d_in[5];
    const float* b1a = (const float*)d_in[6];
    const float* w1b = (const float*)d_in[7];
    const float* b1b = (const float*)d_in[8];
    const float* w2a = (const float*)d_in[9];
    const float* b2a = (const float*)d_in[10];
    const float* w2b = (const float*)d_in[11];
    const float* b2b = (const float*)d_in[12];
    float* out = (float*)d_out;

    const int N = in_sizes[0] / 128;
    const int E = in_sizes[1] / 2;

    unsigned char *w1blob = nullptr, *w2blob = nullptr;
    cudaGetSymbolAddress((void**)&w1blob, g_w1blob);
    cudaGetSymbolAddress((void**)&w2blob, g_w2blob);

    const int NODE_SMEM = (64 * 384 + 16 * 256) * 4;
    cudaFuncSetAttribute(edge_mma_kernel, cudaFuncAttributeMaxDynamicSharedMemorySize, EDGE_SMEM);
    cudaFuncSetAttribute(node_mlp_kernel, cudaFuncAttributeMaxDynamicSharedMemorySize, NODE_SMEM);

    detect_idx_kernel<<<1, 256>>>((const int*)ei);
    zero_kernel<<<1024, 256>>>(N);
    prep_weights_kernel<<<128, 512>>>(w1a, w1blob);
    prep_weights_kernel<<<128, 512>>>(w1b, w2blob);
    edge_mma_kernel<<<(E + 127) / 128, 512, EDGE_SMEM>>>(x, ei, ea, b1a, b1b, E, N);
    node_mlp_kernel<<<(N + 63) / 64, 256, NODE_SMEM>>>(x, w2a, b2a, w2b, b2b, out, N);
}